// round 2
// baseline (speedup 1.0000x reference)
#include <cuda_runtime.h>
#include <math.h>

#define BIGV   100000000.0f
#define GAMMA_ 0.05f
#define INVG_  20.0f
#define WARPP  256.0f
#define K_     4
#define B_     8
#define KB_    32
#define N_     800
#define C_     80
#define S_     128
#define Z_     32

// ---- scratch (device globals; no runtime allocation) ----
__device__ float g_sx[(size_t)KB_ * N_ * C_];   // sigmoid(mel_iters)
__device__ float g_sy[(size_t)B_  * N_ * C_];   // sigmoid(mel_targets)
__device__ float g_x2[KB_ * N_];                // row norms of sx
__device__ float g_y2[B_  * N_];                // row norms of sy
__device__ float g_D [(size_t)KB_ * N_ * N_];   // distance matrices
__device__ float g_d [KB_];                     // DTW costs

// ============================================================
// Kernel 1: sigmoid + squared row norms. One warp per row.
// ============================================================
__global__ void prep_kernel(const float* __restrict__ mel_iters,
                            const float* __restrict__ mel_targets) {
    int wid  = (blockIdx.x * blockDim.x + threadIdx.x) >> 5;
    int lane = threadIdx.x & 31;
    const int xrows = KB_ * N_;
    const int total = xrows + B_ * N_;
    if (wid >= total) return;

    const float* src;
    float* dst;
    float* nrm;
    if (wid < xrows) {
        src = mel_iters + (size_t)wid * C_;
        dst = g_sx      + (size_t)wid * C_;
        nrm = g_x2 + wid;
    } else {
        int r = wid - xrows;
        src = mel_targets + (size_t)r * C_;
        dst = g_sy        + (size_t)r * C_;
        nrm = g_y2 + r;
    }
    float acc = 0.f;
    #pragma unroll
    for (int c0 = 0; c0 < C_; c0 += 32) {
        int c = c0 + lane;
        if (c < C_) {
            float v = src[c];
            float s = 1.f / (1.f + expf(-v));
            dst[c] = s;
            acc = fmaf(s, s, acc);
        }
    }
    #pragma unroll
    for (int o = 16; o; o >>= 1) acc += __shfl_xor_sync(0xffffffffu, acc, o);
    if (lane == 0) *nrm = acc;
}

// ============================================================
// Kernel 2: D[kb][n][m] = x2[n] + y2[m] - 2 * <sx[n], sy[m]>
// 64x64 tile, K=80 one-shot, 256 threads, 4x4 microtile.
// smem transposed [k][row] with stride 68 (16B aligned) so the
// microtile fragments are LDS.128.
// ============================================================
#define PAD_ 68

__global__ void __launch_bounds__(256) dist_gemm_kernel() {
    __shared__ float sA[80 * PAD_];
    __shared__ float sB[80 * PAD_];

    const int kb = blockIdx.z;
    const int b  = kb & 7;
    const int m0 = blockIdx.x * 64;
    const int n0 = blockIdx.y * 64;
    const int t  = threadIdx.x;

    const float4* xbase = (const float4*)(g_sx + (size_t)kb * N_ * C_ + (size_t)n0 * C_);
    const float4* ybase = (const float4*)(g_sy + (size_t)b  * N_ * C_ + (size_t)m0 * C_);

    // Load 64x80 tiles: float4 global reads, scalar smem scatter
    for (int e = t; e < 64 * 20; e += 256) {
        int r  = e / 20;        // row 0..63
        int c4 = e - r * 20;    // float4 col
        bool nok = (n0 + r < N_);
        bool mok = (m0 + r < N_);
        float4 xv = nok ? xbase[r * 20 + c4] : make_float4(0.f,0.f,0.f,0.f);
        float4 yv = mok ? ybase[r * 20 + c4] : make_float4(0.f,0.f,0.f,0.f);
        int c = c4 * 4;
        sA[(c+0)*PAD_ + r] = xv.x; sA[(c+1)*PAD_ + r] = xv.y;
        sA[(c+2)*PAD_ + r] = xv.z; sA[(c+3)*PAD_ + r] = xv.w;
        sB[(c+0)*PAD_ + r] = yv.x; sB[(c+1)*PAD_ + r] = yv.y;
        sB[(c+2)*PAD_ + r] = yv.z; sB[(c+3)*PAD_ + r] = yv.w;
    }
    __syncthreads();

    const int tx = t & 15;   // m microtile
    const int ty = t >> 4;   // n microtile

    float acc[4][4];
    #pragma unroll
    for (int i = 0; i < 4; i++)
        #pragma unroll
        for (int j = 0; j < 4; j++) acc[i][j] = 0.f;

    const float4* a4 = (const float4*)(sA + ty * 4);
    const float4* b4 = (const float4*)(sB + tx * 4);

    #pragma unroll 4
    for (int k = 0; k < 80; k++) {
        float4 a  = a4[k * (PAD_/4)];
        float4 bb = b4[k * (PAD_/4)];
        acc[0][0] = fmaf(a.x, bb.x, acc[0][0]);
        acc[0][1] = fmaf(a.x, bb.y, acc[0][1]);
        acc[0][2] = fmaf(a.x, bb.z, acc[0][2]);
        acc[0][3] = fmaf(a.x, bb.w, acc[0][3]);
        acc[1][0] = fmaf(a.y, bb.x, acc[1][0]);
        acc[1][1] = fmaf(a.y, bb.y, acc[1][1]);
        acc[1][2] = fmaf(a.y, bb.z, acc[1][2]);
        acc[1][3] = fmaf(a.y, bb.w, acc[1][3]);
        acc[2][0] = fmaf(a.z, bb.x, acc[2][0]);
        acc[2][1] = fmaf(a.z, bb.y, acc[2][1]);
        acc[2][2] = fmaf(a.z, bb.z, acc[2][2]);
        acc[2][3] = fmaf(a.z, bb.w, acc[2][3]);
        acc[3][0] = fmaf(a.w, bb.x, acc[3][0]);
        acc[3][1] = fmaf(a.w, bb.y, acc[3][1]);
        acc[3][2] = fmaf(a.w, bb.z, acc[3][2]);
        acc[3][3] = fmaf(a.w, bb.w, acc[3][3]);
    }

    float* Dp = g_D + (size_t)kb * N_ * N_;
    int mbase = m0 + tx * 4;
    float y0 = 0.f, y1 = 0.f, y2v = 0.f, y3 = 0.f;
    if (mbase + 3 < N_) {
        y0 = g_y2[b * N_ + mbase + 0];
        y1 = g_y2[b * N_ + mbase + 1];
        y2v = g_y2[b * N_ + mbase + 2];
        y3 = g_y2[b * N_ + mbase + 3];
    }
    #pragma unroll
    for (int i = 0; i < 4; i++) {
        int n = n0 + ty * 4 + i;
        if (n >= N_) continue;
        float xn = g_x2[kb * N_ + n];
        if (mbase + 3 < N_) {
            float4 v;
            v.x = xn + y0  - 2.f * acc[i][0];
            v.y = xn + y1  - 2.f * acc[i][1];
            v.z = xn + y2v - 2.f * acc[i][2];
            v.w = xn + y3  - 2.f * acc[i][3];
            *reinterpret_cast<float4*>(&Dp[(size_t)n * N_ + mbase]) = v;
        } else {
            #pragma unroll
            for (int j = 0; j < 4; j++) {
                int m = mbase + j;
                if (m < N_)
                    Dp[(size_t)n * N_ + m] = xn + g_y2[b * N_ + m] - 2.f * acc[i][j];
            }
        }
    }
}

// ============================================================
// Kernel 3: soft-DTW wavefront. 1 CTA per pair, 200 threads,
// 4 rows per thread held in registers. Only per-thread top-row
// values cross through smem (ping-pong, 1 barrier/diagonal).
// two[i-1] boundary = previous iteration's one[i-1] (reg carry).
// Softmin short-circuits to min when second-smallest arm exceeds
// min by > 1.0 (fp32 logsumexp is then exactly min).
// ============================================================
#define RPT_ 4
#define NT_  (N_ / RPT_)   // 200 threads

__global__ void __launch_bounds__(NT_) dtw_kernel() {
    __shared__ float bnd[2][NT_];

    const int kb = blockIdx.x;
    const int t  = threadIdx.x;
    const int i0 = RPT_ * t + 1;          // bottom row (1-indexed)

    float one_r[RPT_], two_r[RPT_];
    #pragma unroll
    for (int r = 0; r < RPT_; r++) { one_r[r] = BIGV; two_r[r] = BIGV; }
    float b_two;   // two[i0-1] for current diagonal

    bnd[0][t] = BIGV;
    bnd[1][t] = BIGV;
    __syncthreads();

    const float* Dbase = g_D + (size_t)kb * N_ * N_;

    for (int d = 2; d <= 2 * N_; d++) {
        // one[i0-1]: neighbor's top row from diagonal d-1
        float b_one = (t == 0) ? BIGV : bnd[(d - 1) & 1][t - 1];
        if (t == 0) b_two = (d == 2) ? 0.f : BIGV;

        float new_r[RPT_];
        #pragma unroll
        for (int r = 0; r < RPT_; r++) {
            int i = i0 + r;
            int j = d - i;
            float nr = BIGV;
            if (j >= 1 && j <= N_) {
                float a = (r == 0) ? b_two : two_r[r - 1];
                float bu = ((r == 0) ? b_one : one_r[r - 1]) + WARPP;
                float c = one_r[r] + WARPP;
                float m = fminf(a, fminf(bu, c));
                float sm = m;
                float d1 = a - m, d2 = bu - m, d3 = c - m;
                float second = d1 + d2 + d3 - fmaxf(d1, fmaxf(d2, d3));
                if (second < 1.0f) {
                    sm = m - GAMMA_ * logf(expf(-d1 * INVG_) +
                                           expf(-d2 * INVG_) +
                                           expf(-d3 * INVG_));
                }
                nr = __ldg(Dbase + (size_t)(i - 1) * N_ + (j - 1)) + sm;
            }
            new_r[r] = nr;
        }

        // shift: two <- one, one <- new; boundary carry
        #pragma unroll
        for (int r = 0; r < RPT_; r++) { two_r[r] = one_r[r]; one_r[r] = new_r[r]; }
        b_two = b_one;

        bnd[d & 1][t] = one_r[RPT_ - 1];
        __syncthreads();
    }

    if (t == NT_ - 1) g_d[kb] = one_r[RPT_ - 1];   // R[N, M]
}

// ============================================================
// Kernel 4: finalize scalar losses (parallelized).
// ============================================================
__global__ void finalize_kernel(const int* __restrict__ mel_lens,
                                const int* __restrict__ src_lens,
                                const float* __restrict__ durations,
                                const float* __restrict__ mus,
                                const float* __restrict__ log_vars,
                                const int* __restrict__ step_p,
                                float* __restrict__ out) {
    __shared__ float s_kl[8];
    __shared__ float s_dur[B_];
    __shared__ float s_d[KB_];

    int t    = threadIdx.x;      // 256 threads
    int lane = t & 31;
    int w    = t >> 5;           // 8 warps

    // KL: one element per thread
    {
        float lv = log_vars[t];
        float mu = mus[t];
        float kl = 1.f + lv - mu * mu - expf(lv);
        #pragma unroll
        for (int o = 16; o; o >>= 1) kl += __shfl_xor_sync(0xffffffffu, kl, o);
        if (lane == 0) s_kl[w] = kl;
    }

    // duration sums: warp w handles batch b = w
    {
        float ds = durations[w * S_ + lane] + durations[w * S_ + 32 + lane]
                 + durations[w * S_ + 64 + lane] + durations[w * S_ + 96 + lane];
        #pragma unroll
        for (int o = 16; o; o >>= 1) ds += __shfl_xor_sync(0xffffffffu, ds, o);
        if (lane == 0) s_dur[w] = ds;
    }

    if (t < KB_) s_d[t] = g_d[t];
    __syncthreads();

    if (t == 0) {
        float klsum = 0.f;
        #pragma unroll
        for (int i = 0; i < 8; i++) klsum += s_kl[i];
        float kl_loss = -0.5f * klsum;

        float sum_d = 0.f;
        #pragma unroll
        for (int p = 0; p < KB_; p++) sum_d += s_d[p];
        float mel_iter_loss = sum_d / (float)B_;   // sum_k mean_b d

        float mel = 0.f, durl = 0.f;
        #pragma unroll
        for (int b = 0; b < B_; b++) {
            float len = (float)mel_lens[b];
            mel += mel_iter_loss / ((float)K_ * len);
            durl += fabsf(s_dur[b] - len) / (float)src_lens[b];
        }
        mel  /= (float)B_;
        durl  = 2.f * durl / (float)B_;

        int step = step_p[0];
        float beta;
        if (step < 2000)       beta = 0.f;
        else if (step >= 8000) beta = 1.f;
        else                   beta = (float)(step - 2000) / 6000.f;

        float total = mel + durl + beta * kl_loss;
        out[0] = total;
        out[1] = mel;
        out[2] = durl;
        out[3] = kl_loss;
        out[4] = beta;
    }
}

// ============================================================
extern "C" void kernel_launch(void* const* d_in, const int* in_sizes, int n_in,
                              void* d_out, int out_size) {
    const float* mel_iters   = (const float*)d_in[0];
    const float* mel_targets = (const float*)d_in[1];
    const int*   mel_lens    = (const int*)  d_in[2];
    const int*   src_lens    = (const int*)  d_in[3];
    const float* durations   = (const float*)d_in[4];
    const float* mus         = (const float*)d_in[5];
    const float* log_vars    = (const float*)d_in[6];
    const int*   step        = (const int*)  d_in[7];
    float*       out         = (float*)d_out;

    (void)in_sizes; (void)n_in; (void)out_size;

    const int total_rows = KB_ * N_ + B_ * N_;
    const int wpb = 8;
    prep_kernel<<<(total_rows + wpb - 1) / wpb, wpb * 32>>>(mel_iters, mel_targets);

    dim3 g((N_ + 63) / 64, (N_ + 63) / 64, KB_);
    dist_gemm_kernel<<<g, 256>>>();

    dtw_kernel<<<KB_, NT_>>>();

    finalize_kernel<<<1, 256>>>(mel_lens, src_lens, durations, mus, log_vars, step, out);
}

// round 3
// speedup vs baseline: 1.0200x; 1.0200x over previous
#include <cuda_runtime.h>
#include <math.h>

#define BIGV   100000000.0f
#define GAMMA_ 0.05f
#define INVG_  20.0f
#define WARPP  256.0f
#define K_     4
#define B_     8
#define KB_    32
#define N_     800
#define C_     80
#define S_     128
#define Z_     32

// ---- scratch (device globals; no runtime allocation) ----
__device__ float g_sx[(size_t)KB_ * N_ * C_];   // sigmoid(mel_iters)
__device__ float g_sy[(size_t)B_  * N_ * C_];   // sigmoid(mel_targets)
__device__ float g_x2[KB_ * N_];                // row norms of sx
__device__ float g_y2[B_  * N_];                // row norms of sy
__device__ float g_D [(size_t)KB_ * N_ * N_];   // distance matrices
__device__ float g_d [KB_];                     // DTW costs

// ============================================================
// Kernel 1: sigmoid + squared row norms. One warp per row.
// ============================================================
__global__ void prep_kernel(const float* __restrict__ mel_iters,
                            const float* __restrict__ mel_targets) {
    int wid  = (blockIdx.x * blockDim.x + threadIdx.x) >> 5;
    int lane = threadIdx.x & 31;
    const int xrows = KB_ * N_;
    const int total = xrows + B_ * N_;
    if (wid >= total) return;

    const float* src;
    float* dst;
    float* nrm;
    if (wid < xrows) {
        src = mel_iters + (size_t)wid * C_;
        dst = g_sx      + (size_t)wid * C_;
        nrm = g_x2 + wid;
    } else {
        int r = wid - xrows;
        src = mel_targets + (size_t)r * C_;
        dst = g_sy        + (size_t)r * C_;
        nrm = g_y2 + r;
    }
    float acc = 0.f;
    #pragma unroll
    for (int c0 = 0; c0 < C_; c0 += 32) {
        int c = c0 + lane;
        if (c < C_) {
            float v = src[c];
            float s = 1.f / (1.f + expf(-v));
            dst[c] = s;
            acc = fmaf(s, s, acc);
        }
    }
    #pragma unroll
    for (int o = 16; o; o >>= 1) acc += __shfl_xor_sync(0xffffffffu, acc, o);
    if (lane == 0) *nrm = acc;
}

// ============================================================
// Kernel 2: D[kb][n][m] = x2[n] + y2[m] - 2 * <sx[n], sy[m]>
// 64x64 tile, K=80 one-shot, 256 threads, 4x4 microtile.
// smem transposed [k][row] with stride 68 (16B aligned) so the
// microtile fragments are LDS.128.
// ============================================================
#define PAD_ 68

__global__ void __launch_bounds__(256) dist_gemm_kernel() {
    __shared__ float sA[80 * PAD_];
    __shared__ float sB[80 * PAD_];

    const int kb = blockIdx.z;
    const int b  = kb & 7;
    const int m0 = blockIdx.x * 64;
    const int n0 = blockIdx.y * 64;
    const int t  = threadIdx.x;

    const float4* xbase = (const float4*)(g_sx + (size_t)kb * N_ * C_ + (size_t)n0 * C_);
    const float4* ybase = (const float4*)(g_sy + (size_t)b  * N_ * C_ + (size_t)m0 * C_);

    // Load 64x80 tiles: float4 global reads, scalar smem scatter
    for (int e = t; e < 64 * 20; e += 256) {
        int r  = e / 20;        // row 0..63
        int c4 = e - r * 20;    // float4 col
        bool nok = (n0 + r < N_);
        bool mok = (m0 + r < N_);
        float4 xv = nok ? xbase[r * 20 + c4] : make_float4(0.f,0.f,0.f,0.f);
        float4 yv = mok ? ybase[r * 20 + c4] : make_float4(0.f,0.f,0.f,0.f);
        int c = c4 * 4;
        sA[(c+0)*PAD_ + r] = xv.x; sA[(c+1)*PAD_ + r] = xv.y;
        sA[(c+2)*PAD_ + r] = xv.z; sA[(c+3)*PAD_ + r] = xv.w;
        sB[(c+0)*PAD_ + r] = yv.x; sB[(c+1)*PAD_ + r] = yv.y;
        sB[(c+2)*PAD_ + r] = yv.z; sB[(c+3)*PAD_ + r] = yv.w;
    }
    __syncthreads();

    const int tx = t & 15;   // m microtile
    const int ty = t >> 4;   // n microtile

    float acc[4][4];
    #pragma unroll
    for (int i = 0; i < 4; i++)
        #pragma unroll
        for (int j = 0; j < 4; j++) acc[i][j] = 0.f;

    const float4* a4 = (const float4*)(sA + ty * 4);
    const float4* b4 = (const float4*)(sB + tx * 4);

    #pragma unroll 4
    for (int k = 0; k < 80; k++) {
        float4 a  = a4[k * (PAD_/4)];
        float4 bb = b4[k * (PAD_/4)];
        acc[0][0] = fmaf(a.x, bb.x, acc[0][0]);
        acc[0][1] = fmaf(a.x, bb.y, acc[0][1]);
        acc[0][2] = fmaf(a.x, bb.z, acc[0][2]);
        acc[0][3] = fmaf(a.x, bb.w, acc[0][3]);
        acc[1][0] = fmaf(a.y, bb.x, acc[1][0]);
        acc[1][1] = fmaf(a.y, bb.y, acc[1][1]);
        acc[1][2] = fmaf(a.y, bb.z, acc[1][2]);
        acc[1][3] = fmaf(a.y, bb.w, acc[1][3]);
        acc[2][0] = fmaf(a.z, bb.x, acc[2][0]);
        acc[2][1] = fmaf(a.z, bb.y, acc[2][1]);
        acc[2][2] = fmaf(a.z, bb.z, acc[2][2]);
        acc[2][3] = fmaf(a.z, bb.w, acc[2][3]);
        acc[3][0] = fmaf(a.w, bb.x, acc[3][0]);
        acc[3][1] = fmaf(a.w, bb.y, acc[3][1]);
        acc[3][2] = fmaf(a.w, bb.z, acc[3][2]);
        acc[3][3] = fmaf(a.w, bb.w, acc[3][3]);
    }

    float* Dp = g_D + (size_t)kb * N_ * N_;
    int mbase = m0 + tx * 4;
    float y0 = 0.f, y1 = 0.f, y2v = 0.f, y3 = 0.f;
    if (mbase + 3 < N_) {
        y0 = g_y2[b * N_ + mbase + 0];
        y1 = g_y2[b * N_ + mbase + 1];
        y2v = g_y2[b * N_ + mbase + 2];
        y3 = g_y2[b * N_ + mbase + 3];
    }
    #pragma unroll
    for (int i = 0; i < 4; i++) {
        int n = n0 + ty * 4 + i;
        if (n >= N_) continue;
        float xn = g_x2[kb * N_ + n];
        if (mbase + 3 < N_) {
            float4 v;
            v.x = xn + y0  - 2.f * acc[i][0];
            v.y = xn + y1  - 2.f * acc[i][1];
            v.z = xn + y2v - 2.f * acc[i][2];
            v.w = xn + y3  - 2.f * acc[i][3];
            *reinterpret_cast<float4*>(&Dp[(size_t)n * N_ + mbase]) = v;
        } else {
            #pragma unroll
            for (int j = 0; j < 4; j++) {
                int m = mbase + j;
                if (m < N_)
                    Dp[(size_t)n * N_ + m] = xn + g_y2[b * N_ + m] - 2.f * acc[i][j];
            }
        }
    }
}

// ============================================================
// Kernel 3: soft-DTW wavefront. 1 CTA per pair, 200 threads,
// 4 rows per thread held in registers. Only per-thread top-row
// values cross through smem (ping-pong, 1 barrier/diagonal).
// two[i-1] boundary = previous iteration's one[i-1] (reg carry).
// Softmin short-circuits to min when second-smallest arm exceeds
// min by > 1.0 (fp32 logsumexp is then exactly min).
// ============================================================
#define RPT_ 4
#define NT_  (N_ / RPT_)   // 200 threads

__global__ void __launch_bounds__(NT_) dtw_kernel() {
    __shared__ float bnd[2][NT_];

    const int kb = blockIdx.x;
    const int t  = threadIdx.x;
    const int i0 = RPT_ * t + 1;          // bottom row (1-indexed)

    float one_r[RPT_], two_r[RPT_];
    #pragma unroll
    for (int r = 0; r < RPT_; r++) { one_r[r] = BIGV; two_r[r] = BIGV; }
    float b_two;   // two[i0-1] for current diagonal

    bnd[0][t] = BIGV;
    bnd[1][t] = BIGV;
    __syncthreads();

    const float* Dbase = g_D + (size_t)kb * N_ * N_;

    for (int d = 2; d <= 2 * N_; d++) {
        // one[i0-1]: neighbor's top row from diagonal d-1
        float b_one = (t == 0) ? BIGV : bnd[(d - 1) & 1][t - 1];
        if (t == 0) b_two = (d == 2) ? 0.f : BIGV;

        float new_r[RPT_];
        #pragma unroll
        for (int r = 0; r < RPT_; r++) {
            int i = i0 + r;
            int j = d - i;
            float nr = BIGV;
            if (j >= 1 && j <= N_) {
                float a = (r == 0) ? b_two : two_r[r - 1];
                float bu = ((r == 0) ? b_one : one_r[r - 1]) + WARPP;
                float c = one_r[r] + WARPP;
                float m = fminf(a, fminf(bu, c));
                float sm = m;
                float d1 = a - m, d2 = bu - m, d3 = c - m;
                float second = d1 + d2 + d3 - fmaxf(d1, fmaxf(d2, d3));
                if (second < 1.0f) {
                    sm = m - GAMMA_ * logf(expf(-d1 * INVG_) +
                                           expf(-d2 * INVG_) +
                                           expf(-d3 * INVG_));
                }
                nr = __ldg(Dbase + (size_t)(i - 1) * N_ + (j - 1)) + sm;
            }
            new_r[r] = nr;
        }

        // shift: two <- one, one <- new; boundary carry
        #pragma unroll
        for (int r = 0; r < RPT_; r++) { two_r[r] = one_r[r]; one_r[r] = new_r[r]; }
        b_two = b_one;

        bnd[d & 1][t] = one_r[RPT_ - 1];
        __syncthreads();
    }

    if (t == NT_ - 1) g_d[kb] = one_r[RPT_ - 1];   // R[N, M]
}

// ============================================================
// Kernel 4: finalize scalar losses (parallelized).
// ============================================================
__global__ void finalize_kernel(const int* __restrict__ mel_lens,
                                const int* __restrict__ src_lens,
                                const float* __restrict__ durations,
                                const float* __restrict__ mus,
                                const float* __restrict__ log_vars,
                                const int* __restrict__ step_p,
                                float* __restrict__ out) {
    __shared__ float s_kl[8];
    __shared__ float s_dur[B_];
    __shared__ float s_d[KB_];

    int t    = threadIdx.x;      // 256 threads
    int lane = t & 31;
    int w    = t >> 5;           // 8 warps

    // KL: one element per thread
    {
        float lv = log_vars[t];
        float mu = mus[t];
        float kl = 1.f + lv - mu * mu - expf(lv);
        #pragma unroll
        for (int o = 16; o; o >>= 1) kl += __shfl_xor_sync(0xffffffffu, kl, o);
        if (lane == 0) s_kl[w] = kl;
    }

    // duration sums: warp w handles batch b = w
    {
        float ds = durations[w * S_ + lane] + durations[w * S_ + 32 + lane]
                 + durations[w * S_ + 64 + lane] + durations[w * S_ + 96 + lane];
        #pragma unroll
        for (int o = 16; o; o >>= 1) ds += __shfl_xor_sync(0xffffffffu, ds, o);
        if (lane == 0) s_dur[w] = ds;
    }

    if (t < KB_) s_d[t] = g_d[t];
    __syncthreads();

    if (t == 0) {
        float klsum = 0.f;
        #pragma unroll
        for (int i = 0; i < 8; i++) klsum += s_kl[i];
        float kl_loss = -0.5f * klsum;

        float sum_d = 0.f;
        #pragma unroll
        for (int p = 0; p < KB_; p++) sum_d += s_d[p];
        float mel_iter_loss = sum_d / (float)B_;   // sum_k mean_b d

        float mel = 0.f, durl = 0.f;
        #pragma unroll
        for (int b = 0; b < B_; b++) {
            float len = (float)mel_lens[b];
            mel += mel_iter_loss / ((float)K_ * len);
            durl += fabsf(s_dur[b] - len) / (float)src_lens[b];
        }
        mel  /= (float)B_;
        durl  = 2.f * durl / (float)B_;

        int step = step_p[0];
        float beta;
        if (step < 2000)       beta = 0.f;
        else if (step >= 8000) beta = 1.f;
        else                   beta = (float)(step - 2000) / 6000.f;

        float total = mel + durl + beta * kl_loss;
        out[0] = total;
        out[1] = mel;
        out[2] = durl;
        out[3] = kl_loss;
        out[4] = beta;
    }
}

// ============================================================
extern "C" void kernel_launch(void* const* d_in, const int* in_sizes, int n_in,
                              void* d_out, int out_size) {
    const float* mel_iters   = (const float*)d_in[0];
    const float* mel_targets = (const float*)d_in[1];
    const int*   mel_lens    = (const int*)  d_in[2];
    const int*   src_lens    = (const int*)  d_in[3];
    const float* durations   = (const float*)d_in[4];
    const float* mus         = (const float*)d_in[5];
    const float* log_vars    = (const float*)d_in[6];
    const int*   step        = (const int*)  d_in[7];
    float*       out         = (float*)d_out;

    (void)in_sizes; (void)n_in; (void)out_size;

    const int total_rows = KB_ * N_ + B_ * N_;
    const int wpb = 8;
    prep_kernel<<<(total_rows + wpb - 1) / wpb, wpb * 32>>>(mel_iters, mel_targets);

    dim3 g((N_ + 63) / 64, (N_ + 63) / 64, KB_);
    dist_gemm_kernel<<<g, 256>>>();

    dtw_kernel<<<KB_, NT_>>>();

    finalize_kernel<<<1, 256>>>(mel_lens, src_lens, durations, mus, log_vars, step, out);
}

// round 4
// speedup vs baseline: 2.0358x; 1.9959x over previous
#include <cuda_runtime.h>
#include <math.h>

#define BIGV   100000000.0f
#define GAMMA_ 0.05f
#define INVG_  20.0f
#define WARPP  256.0f
#define K_     4
#define B_     8
#define KB_    32
#define N_     800
#define C_     80
#define S_     128
#define Z_     32

// ---- scratch (device globals; no runtime allocation) ----
__device__ float g_sx[(size_t)KB_ * N_ * C_];   // sigmoid(mel_iters)
__device__ float g_sy[(size_t)B_  * N_ * C_];   // sigmoid(mel_targets)
__device__ float g_x2[KB_ * N_];                // row norms of sx
__device__ float g_y2[B_  * N_];                // row norms of sy
__device__ float g_D [(size_t)KB_ * N_ * N_];   // distance matrices
__device__ float g_d [KB_];                     // DTW costs

// ============================================================
// Kernel 1: sigmoid + squared row norms. One warp per row.
// (identical to the 1209us version)
// ============================================================
__global__ void prep_kernel(const float* __restrict__ mel_iters,
                            const float* __restrict__ mel_targets) {
    int wid  = (blockIdx.x * blockDim.x + threadIdx.x) >> 5;
    int lane = threadIdx.x & 31;
    const int xrows = KB_ * N_;
    const int total = xrows + B_ * N_;
    if (wid >= total) return;

    const float* src;
    float* dst;
    float* nrm;
    if (wid < xrows) {
        src = mel_iters + (size_t)wid * C_;
        dst = g_sx      + (size_t)wid * C_;
        nrm = g_x2 + wid;
    } else {
        int r = wid - xrows;
        src = mel_targets + (size_t)r * C_;
        dst = g_sy        + (size_t)r * C_;
        nrm = g_y2 + r;
    }
    float acc = 0.f;
    for (int c = lane; c < C_; c += 32) {
        float v = src[c];
        float s = 1.f / (1.f + expf(-v));
        dst[c] = s;
        acc += s * s;
    }
    #pragma unroll
    for (int o = 16; o; o >>= 1) acc += __shfl_xor_sync(0xffffffffu, acc, o);
    if (lane == 0) *nrm = acc;
}

// ============================================================
// Kernel 2: D[kb][n][m] = x2[n] + y2[m] - 2 * <sx[n], sy[m]>
// (identical to the 1209us version: 64x64 tile, pad 65, scalar LDS)
// ============================================================
__global__ void __launch_bounds__(256) dist_gemm_kernel() {
    __shared__ float sA[80 * 65];   // sA[c*65 + local_n]
    __shared__ float sB[80 * 65];   // sB[c*65 + local_m]

    const int kb = blockIdx.z;
    const int b  = kb & 7;
    const int m0 = blockIdx.x * 64;
    const int n0 = blockIdx.y * 64;
    const int t  = threadIdx.x;

    const float* xbase = g_sx + (size_t)kb * N_ * C_ + (size_t)n0 * C_;
    const float* ybase = g_sy + (size_t)b  * N_ * C_ + (size_t)m0 * C_;

    for (int e = t; e < 64 * 80; e += 256) {
        int r = e / 80;
        int c = e - r * 80;
        float xv = (n0 + r < N_) ? xbase[r * C_ + c] : 0.f;
        float yv = (m0 + r < N_) ? ybase[r * C_ + c] : 0.f;
        sA[c * 65 + r] = xv;
        sB[c * 65 + r] = yv;
    }
    __syncthreads();

    const int tx = t & 15;   // m microtile
    const int ty = t >> 4;   // n microtile

    float acc[4][4];
    #pragma unroll
    for (int i = 0; i < 4; i++)
        #pragma unroll
        for (int j = 0; j < 4; j++) acc[i][j] = 0.f;

    #pragma unroll 8
    for (int k = 0; k < 80; k++) {
        float a[4], bb[4];
        #pragma unroll
        for (int i = 0; i < 4; i++) a[i]  = sA[k * 65 + ty * 4 + i];
        #pragma unroll
        for (int j = 0; j < 4; j++) bb[j] = sB[k * 65 + tx * 4 + j];
        #pragma unroll
        for (int i = 0; i < 4; i++)
            #pragma unroll
            for (int j = 0; j < 4; j++)
                acc[i][j] = fmaf(a[i], bb[j], acc[i][j]);
    }

    float* Dp = g_D + (size_t)kb * N_ * N_;
    #pragma unroll
    for (int i = 0; i < 4; i++) {
        int n = n0 + ty * 4 + i;
        if (n >= N_) continue;
        float xn = g_x2[kb * N_ + n];
        int mbase = m0 + tx * 4;
        if (mbase + 3 < N_) {
            float4 v;
            v.x = xn + g_y2[b * N_ + mbase + 0] - 2.f * acc[i][0];
            v.y = xn + g_y2[b * N_ + mbase + 1] - 2.f * acc[i][1];
            v.z = xn + g_y2[b * N_ + mbase + 2] - 2.f * acc[i][2];
            v.w = xn + g_y2[b * N_ + mbase + 3] - 2.f * acc[i][3];
            *reinterpret_cast<float4*>(&Dp[(size_t)n * N_ + mbase]) = v;
        } else {
            #pragma unroll
            for (int j = 0; j < 4; j++) {
                int m = mbase + j;
                if (m < N_)
                    Dp[(size_t)n * N_ + m] = xn + g_y2[b * N_ + m] - 2.f * acc[i][j];
            }
        }
    }
}

// ============================================================
// Kernel 3: soft-DTW anti-diagonal wavefront. 1 CTA per pair,
// 800 threads, rolling 3 rows in smem (structure identical to
// the 1209us version). ONE change: the D value for diagonal d
// is prefetched 4 diagonals ahead into registers (clamped
// addresses), so the global-load latency is off the per-diagonal
// critical path. Diagonal loop unrolled by 4 with a uniform
// "dd <= 2N" guard so barriers stay uniform.
// ============================================================
__global__ void __launch_bounds__(800) dtw_kernel() {
    __shared__ float buf[3][N_ + 1];
    const int kb = blockIdx.x;
    const int t  = threadIdx.x;
    const int i  = t + 1;

    for (int idx = t; idx <= N_; idx += 800) {
        buf[0][idx] = BIGV;
        buf[1][idx] = BIGV;
        buf[2][idx] = BIGV;
    }
    if (t == 0) buf[0][0] = 0.f;
    __syncthreads();

    float* two = buf[0];
    float* one = buf[1];
    float* nw  = buf[2];

    // Drow[j] = D[i-1][j-1]
    const float* Drow = g_D + (size_t)kb * N_ * N_ + (size_t)(i - 1) * N_ - 1;

    // clamped load helper indices: j valid in [1, N_]
    #define CLAMP_J(jj) ( (jj) < 1 ? 1 : ((jj) > N_ ? N_ : (jj)) )

    // prefetch buffer: cur holds D for diagonals d0..d0+3 of this thread
    float cur0, cur1, cur2, cur3;
    {
        int j = 2 - i;   // j at d = 2
        cur0 = __ldg(Drow + CLAMP_J(j + 0));
        cur1 = __ldg(Drow + CLAMP_J(j + 1));
        cur2 = __ldg(Drow + CLAMP_J(j + 2));
        cur3 = __ldg(Drow + CLAMP_J(j + 3));
    }

    float res = 0.f;
    for (int d0 = 2; d0 <= 2 * N_; d0 += 4) {
        // issue prefetch for next group (consumed 1-4 diagonals later)
        int jn = d0 + 4 - i;
        float nx0 = __ldg(Drow + CLAMP_J(jn + 0));
        float nx1 = __ldg(Drow + CLAMP_J(jn + 1));
        float nx2 = __ldg(Drow + CLAMP_J(jn + 2));
        float nx3 = __ldg(Drow + CLAMP_J(jn + 3));

        #pragma unroll
        for (int r = 0; r < 4; r++) {
            int dd = d0 + r;
            if (dd <= 2 * N_) {            // uniform across block
                int j = dd - i;
                float rv = BIGV;
                if (j >= 1 && j <= N_) {
                    float a = two[i - 1];
                    float b = one[i - 1] + WARPP;
                    float c = one[i]     + WARPP;
                    float m = fminf(a, fminf(b, c));
                    float sm = m;
                    float d1 = a - m, d2 = b - m, d3 = c - m;
                    float second = d1 + d2 + d3 - fmaxf(d1, fmaxf(d2, d3));
                    if (second < 1.0f) {
                        sm = m - GAMMA_ * logf(expf(-d1 * INVG_) +
                                               expf(-d2 * INVG_) +
                                               expf(-d3 * INVG_));
                    }
                    float Dv = (r == 0) ? cur0 : (r == 1) ? cur1 : (r == 2) ? cur2 : cur3;
                    rv = Dv + sm;
                }
                nw[i] = rv;
                if (t == 0) nw[0] = BIGV;
                res = rv;
                __syncthreads();
                float* tmp = two; two = one; one = nw; nw = tmp;
            }
        }
        cur0 = nx0; cur1 = nx1; cur2 = nx2; cur3 = nx3;
    }
    if (t == N_ - 1) g_d[kb] = res;   // R[N, M]
    #undef CLAMP_J
}

// ============================================================
// Kernel 4: finalize scalar losses (parallel version, measured
// 6.5us vs 25.9us serial).
// ============================================================
__global__ void finalize_kernel(const int* __restrict__ mel_lens,
                                const int* __restrict__ src_lens,
                                const float* __restrict__ durations,
                                const float* __restrict__ mus,
                                const float* __restrict__ log_vars,
                                const int* __restrict__ step_p,
                                float* __restrict__ out) {
    __shared__ float s_kl[8];
    __shared__ float s_dur[B_];
    __shared__ float s_d[KB_];

    int t    = threadIdx.x;      // 256 threads
    int lane = t & 31;
    int w    = t >> 5;           // 8 warps

    {
        float lv = log_vars[t];
        float mu = mus[t];
        float kl = 1.f + lv - mu * mu - expf(lv);
        #pragma unroll
        for (int o = 16; o; o >>= 1) kl += __shfl_xor_sync(0xffffffffu, kl, o);
        if (lane == 0) s_kl[w] = kl;
    }

    {
        float ds = durations[w * S_ + lane] + durations[w * S_ + 32 + lane]
                 + durations[w * S_ + 64 + lane] + durations[w * S_ + 96 + lane];
        #pragma unroll
        for (int o = 16; o; o >>= 1) ds += __shfl_xor_sync(0xffffffffu, ds, o);
        if (lane == 0) s_dur[w] = ds;
    }

    if (t < KB_) s_d[t] = g_d[t];
    __syncthreads();

    if (t == 0) {
        float klsum = 0.f;
        #pragma unroll
        for (int i = 0; i < 8; i++) klsum += s_kl[i];
        float kl_loss = -0.5f * klsum;

        float sum_d = 0.f;
        #pragma unroll
        for (int p = 0; p < KB_; p++) sum_d += s_d[p];
        float mel_iter_loss = sum_d / (float)B_;   // sum_k mean_b d

        float mel = 0.f, durl = 0.f;
        #pragma unroll
        for (int b = 0; b < B_; b++) {
            float len = (float)mel_lens[b];
            mel += mel_iter_loss / ((float)K_ * len);
            durl += fabsf(s_dur[b] - len) / (float)src_lens[b];
        }
        mel  /= (float)B_;
        durl  = 2.f * durl / (float)B_;

        int step = step_p[0];
        float beta;
        if (step < 2000)       beta = 0.f;
        else if (step >= 8000) beta = 1.f;
        else                   beta = (float)(step - 2000) / 6000.f;

        float total = mel + durl + beta * kl_loss;
        out[0] = total;
        out[1] = mel;
        out[2] = durl;
        out[3] = kl_loss;
        out[4] = beta;
    }
}

// ============================================================
extern "C" void kernel_launch(void* const* d_in, const int* in_sizes, int n_in,
                              void* d_out, int out_size) {
    const float* mel_iters   = (const float*)d_in[0];
    const float* mel_targets = (const float*)d_in[1];
    const int*   mel_lens    = (const int*)  d_in[2];
    const int*   src_lens    = (const int*)  d_in[3];
    const float* durations   = (const float*)d_in[4];
    const float* mus         = (const float*)d_in[5];
    const float* log_vars    = (const float*)d_in[6];
    const int*   step        = (const int*)  d_in[7];
    float*       out         = (float*)d_out;

    (void)in_sizes; (void)n_in; (void)out_size;

    const int total_rows = KB_ * N_ + B_ * N_;
    const int wpb = 8;
    prep_kernel<<<(total_rows + wpb - 1) / wpb, wpb * 32>>>(mel_iters, mel_targets);

    dim3 g((N_ + 63) / 64, (N_ + 63) / 64, KB_);
    dist_gemm_kernel<<<g, 256>>>();

    dtw_kernel<<<KB_, 800>>>();

    finalize_kernel<<<1, 256>>>(mel_lens, src_lens, durations, mus, log_vars, step, out);
}